// round 6
// baseline (speedup 1.0000x reference)
#include <cuda_runtime.h>

#define SEQ_LEN  512
#define PRED_LEN 192
#define ENC_IN   512
#define BATCH    128
#define CSPLIT   16
#define CH_PER_CTA (ENC_IN / CSPLIT)       // 32 channels -> 8 float4 lanes
#define LANES    (CH_PER_CTA / 4)          // 8
#define NSUB     16                        // row subgroups
#define ROWS_PER_THREAD (SEQ_LEN / NSUB)   // 32
#define NT       (LANES * NSUB)            // 128 threads

// Fused: grid (BATCH, CSPLIT) = 2048 CTAs, block 128, one resident wave
// (14 CTAs/SM). Reads are streaming (__ldcs, evict-first); stores are default
// write-back so the 151 MB output preferentially stays dirty in the 126 MB L2.
__global__ __launch_bounds__(NT, 14)
void fused_trend_kernel(const float* __restrict__ x_enc, float* __restrict__ out) {
    const int b    = blockIdx.x;
    const int cg   = blockIdx.y;
    const int t    = threadIdx.x;
    const int lane = t & (LANES - 1);      // float4 column (0..7)
    const int rsub = t >> 3;               // row subgroup (0..15)
    const int c0   = cg * CH_PER_CTA;

    const size_t SEC = (size_t)BATCH * PRED_LEN * ENC_IN;   // floats per tensor
    const size_t tile_f = (size_t)b * PRED_LEN * ENC_IN + c0;
    const float4 zero = make_float4(0.f, 0.f, 0.f, 0.f);

    // ---- Early: s_out zeros (independent) — land in L2 while reads stream ----
    {
        float4* __restrict__ sou = reinterpret_cast<float4*>(out + 2 * SEC + tile_f);
        #pragma unroll 4
        for (int idx = t; idx < PRED_LEN * LANES; idx += NT) {
            int row = idx >> 3;
            int c4  = idx & (LANES - 1);
            sou[(size_t)row * (ENC_IN / 4) + c4] = zero;
        }
    }

    // ---- Reduction over L: 32 rows/thread, float4 lanes, streaming loads ----
    const float4* __restrict__ px =
        reinterpret_cast<const float4*>(x_enc + (size_t)b * SEQ_LEN * ENC_IN + c0);

    float4 sy  = zero;
    float4 sty = zero;
    #pragma unroll 4
    for (int i = 0; i < ROWS_PER_THREAD; ++i) {
        int r = i * NSUB + rsub;
        float4 v = __ldcs(&px[(size_t)r * (ENC_IN / 4) + lane]);
        float tc = (float)(r - SEQ_LEN);          // t in [-512, -1]
        sy.x += v.x;  sy.y += v.y;  sy.z += v.z;  sy.w += v.w;
        sty.x = fmaf(tc, v.x, sty.x);
        sty.y = fmaf(tc, v.y, sty.y);
        sty.z = fmaf(tc, v.z, sty.z);
        sty.w = fmaf(tc, v.w, sty.w);
    }

    __shared__ float4 red_sy[NSUB][LANES];
    __shared__ float4 red_sty[NSUB][LANES];
    __shared__ float4 sI4[LANES];
    __shared__ float4 sS4[LANES];

    red_sy[rsub][lane]  = sy;
    red_sty[rsub][lane] = sty;
    __syncthreads();

    if (t < LANES) {
        float4 a = red_sy[0][t];
        float4 c = red_sty[0][t];
        #pragma unroll
        for (int k = 1; k < NSUB; ++k) {
            float4 u = red_sy[k][t];
            float4 w = red_sty[k][t];
            a.x += u.x; a.y += u.y; a.z += u.z; a.w += u.w;
            c.x += w.x; c.y += w.y; c.z += w.z; c.w += w.w;
        }
        // Normal-equation constants for t = -512..-1 (exact in fp32):
        const float S0  = 512.0f;
        const float S1  = -131328.0f;
        const float S2  = 44870400.0f;
        const float det = 5726601216.0f;

        float4 I, S;
        I.x = (S2 * a.x - S1 * c.x) / det;  S.x = (S0 * c.x - S1 * a.x) / det;
        I.y = (S2 * a.y - S1 * c.y) / det;  S.y = (S0 * c.y - S1 * a.y) / det;
        I.z = (S2 * a.z - S1 * c.z) / det;  S.z = (S0 * c.z - S1 * a.z) / det;
        I.w = (S2 * a.w - S1 * c.w) / det;  S.w = (S0 * c.w - S1 * a.w) / det;
        sI4[t] = I;
        sS4[t] = S;
    }
    __syncthreads();

    // ---- Write dec_out and t_out (identical values), write-back stores ----
    float4* __restrict__ dec = reinterpret_cast<float4*>(out + tile_f);
    float4* __restrict__ tou = reinterpret_cast<float4*>(out + SEC + tile_f);

    #pragma unroll 4
    for (int idx = t; idx < PRED_LEN * LANES; idx += NT) {
        int row = idx >> 3;
        int c4  = idx & (LANES - 1);
        float tn = (float)(SEQ_LEN - PRED_LEN + row);   // 320..511
        float4 I = sI4[c4];
        float4 S = sS4[c4];
        float4 v;
        v.x = fmaf(S.x, tn, I.x);
        v.y = fmaf(S.y, tn, I.y);
        v.z = fmaf(S.z, tn, I.z);
        v.w = fmaf(S.w, tn, I.w);
        size_t off = (size_t)row * (ENC_IN / 4) + c4;
        dec[off] = v;
        tou[off] = v;
    }
}

extern "C" void kernel_launch(void* const* d_in, const int* in_sizes, int n_in,
                              void* d_out, int out_size) {
    const float* x_enc = (const float*)d_in[0];
    float* out = (float*)d_out;
    fused_trend_kernel<<<dim3(BATCH, CSPLIT), NT>>>(x_enc, out);
}

// round 7
// speedup vs baseline: 1.0350x; 1.0350x over previous
#include <cuda_runtime.h>

#define SEQ_LEN  512
#define PRED_LEN 192
#define ENC_IN   512
#define BATCH    128
#define NF4      (ENC_IN / 4)        // 128 float4 per row
#define LCHUNKS  16
#define ROWS_A   (SEQ_LEN / LCHUNKS) // 32 rows per reduce CTA
#define WCHUNKS  8
#define ROWS_B   (PRED_LEN / WCHUNKS)// 24 rows per write CTA

// Partial sums: [chunk][batch][128 float4 channels]
__device__ float4 g_psy [LCHUNKS][BATCH][NF4];
__device__ float4 g_psty[LCHUNKS][BATCH][NF4];

// ---------------- Kernel A: contiguous partial reduce + s_out zeros ----------
// grid (BATCH, LCHUNKS) = 2048 CTAs, block 128, one resident wave (14/SM).
// Each CTA streams a contiguous 64KB block of x_enc.
__global__ __launch_bounds__(128, 14)
void reduce_kernel(const float* __restrict__ x_enc, float* __restrict__ out) {
    const int b  = blockIdx.x;
    const int ch = blockIdx.y;
    const int t  = threadIdx.x;           // float4 column 0..127
    const int l0 = ch * ROWS_A;

    // ---- s_out zeros: contiguous 1536-float4 slice per CTA ----
    {
        const size_t SEC4 = (size_t)BATCH * PRED_LEN * NF4;     // float4 per tensor
        float4* __restrict__ sou = reinterpret_cast<float4*>(out) + 2 * SEC4
                                   + (size_t)(b * LCHUNKS + ch) * (PRED_LEN * NF4 / LCHUNKS);
        const float4 zero = make_float4(0.f, 0.f, 0.f, 0.f);
        #pragma unroll
        for (int i = 0; i < PRED_LEN * NF4 / LCHUNKS / 128; ++i)  // 12
            __stcs(&sou[i * 128 + t], zero);
    }

    // ---- Contiguous read: rows l0..l0+31, thread t owns f4-col t ----
    const float4* __restrict__ px =
        reinterpret_cast<const float4*>(x_enc) + ((size_t)b * SEQ_LEN + l0) * NF4;

    float4 sy  = make_float4(0.f, 0.f, 0.f, 0.f);
    float4 sty = make_float4(0.f, 0.f, 0.f, 0.f);
    #pragma unroll 4
    for (int r = 0; r < ROWS_A; ++r) {
        float4 v = __ldcs(&px[(size_t)r * NF4 + t]);
        float tc = (float)(l0 + r - SEQ_LEN);        // t in [-512,-1]
        sy.x += v.x;  sy.y += v.y;  sy.z += v.z;  sy.w += v.w;
        sty.x = fmaf(tc, v.x, sty.x);
        sty.y = fmaf(tc, v.y, sty.y);
        sty.z = fmaf(tc, v.z, sty.z);
        sty.w = fmaf(tc, v.w, sty.w);
    }
    g_psy [ch][b][t] = sy;
    g_psty[ch][b][t] = sty;
}

// ---------------- Kernel B: combine + contiguous dec/t_out writes ------------
// grid (BATCH, WCHUNKS) = 1024 CTAs, block 256, one resident wave (7/SM).
__global__ __launch_bounds__(256, 7)
void write_kernel(float* __restrict__ out) {
    const int b  = blockIdx.x;
    const int w  = blockIdx.y;
    const int t  = threadIdx.x;

    __shared__ float4 sI4[NF4];
    __shared__ float4 sS4[NF4];

    if (t < NF4) {
        float4 a = make_float4(0.f, 0.f, 0.f, 0.f);
        float4 c = make_float4(0.f, 0.f, 0.f, 0.f);
        #pragma unroll
        for (int k = 0; k < LCHUNKS; ++k) {
            float4 u = g_psy [k][b][t];
            float4 x = g_psty[k][b][t];
            a.x += u.x; a.y += u.y; a.z += u.z; a.w += u.w;
            c.x += x.x; c.y += x.y; c.z += x.z; c.w += x.w;
        }
        // Normal-equation constants for t = -512..-1 (exact in fp32):
        const float S0  = 512.0f;
        const float S1  = -131328.0f;
        const float S2  = 44870400.0f;
        const float det = 5726601216.0f;

        float4 I, S;
        I.x = (S2 * a.x - S1 * c.x) / det;  S.x = (S0 * c.x - S1 * a.x) / det;
        I.y = (S2 * a.y - S1 * c.y) / det;  S.y = (S0 * c.y - S1 * a.y) / det;
        I.z = (S2 * a.z - S1 * c.z) / det;  S.z = (S0 * c.z - S1 * a.z) / det;
        I.w = (S2 * a.w - S1 * c.w) / det;  S.w = (S0 * c.w - S1 * a.w) / det;
        sI4[t] = I;
        sS4[t] = S;
    }
    __syncthreads();

    const size_t SEC4 = (size_t)BATCH * PRED_LEN * NF4;
    const int r0 = w * ROWS_B;
    float4* __restrict__ dec = reinterpret_cast<float4*>(out)
                               + ((size_t)b * PRED_LEN + r0) * NF4;
    float4* __restrict__ tou = dec + SEC4;

    // 24 rows x 128 f4, contiguous row-major; 256 threads -> 12 iterations.
    #pragma unroll 4
    for (int idx = t; idx < ROWS_B * NF4; idx += 256) {
        int row = idx >> 7;
        int c4  = idx & (NF4 - 1);
        float tn = (float)(SEQ_LEN - PRED_LEN + r0 + row);   // 320..511
        float4 I = sI4[c4];
        float4 S = sS4[c4];
        float4 v;
        v.x = fmaf(S.x, tn, I.x);
        v.y = fmaf(S.y, tn, I.y);
        v.z = fmaf(S.z, tn, I.z);
        v.w = fmaf(S.w, tn, I.w);
        __stcs(&dec[idx], v);
        __stcs(&tou[idx], v);
    }
}

extern "C" void kernel_launch(void* const* d_in, const int* in_sizes, int n_in,
                              void* d_out, int out_size) {
    const float* x_enc = (const float*)d_in[0];
    float* out = (float*)d_out;
    reduce_kernel<<<dim3(BATCH, LCHUNKS), 128>>>(x_enc, out);
    write_kernel<<<dim3(BATCH, WCHUNKS), 256>>>(out);
}

// round 8
// speedup vs baseline: 1.1482x; 1.1094x over previous
#include <cuda_runtime.h>

#define SEQ_LEN  512
#define PRED_LEN 192
#define ENC_IN   512
#define BATCH    128
#define CSPLIT   8
#define CH_PER_CTA (ENC_IN / CSPLIT)       // 64 channels -> 16 float4 lanes
#define LANES    (CH_PER_CTA / 4)          // 16
#define NSUB     16                        // row subgroups
#define ROWS_PER_THREAD (SEQ_LEN / NSUB)   // 32
#define NT       (LANES * NSUB)            // 256 threads

// Fused: grid (BATCH, CSPLIT) = 1024 CTAs, block 256, one resident wave
// (7 CTAs/SM -> 56 warps/SM). 256B-contiguous bursts per 16-lane group.
__global__ __launch_bounds__(NT, 7)
void fused_trend_kernel(const float* __restrict__ x_enc, float* __restrict__ out) {
    const int b    = blockIdx.x;
    const int cg   = blockIdx.y;
    const int t    = threadIdx.x;
    const int lane = t & (LANES - 1);      // float4 column (0..15)
    const int rsub = t >> 4;               // row subgroup (0..15)
    const int c0   = cg * CH_PER_CTA;

    const size_t SEC = (size_t)BATCH * PRED_LEN * ENC_IN;   // floats per tensor
    const size_t tile_f = (size_t)b * PRED_LEN * ENC_IN + c0;
    const float4 zero = make_float4(0.f, 0.f, 0.f, 0.f);

    float4* __restrict__ sou = reinterpret_cast<float4*>(out + 2 * SEC + tile_f);

    // ---- s_out zeros, first half (rows 0..95) — overlaps the read phase ----
    #pragma unroll
    for (int idx = t; idx < (PRED_LEN / 2) * LANES; idx += NT) {
        int row = idx >> 4;
        int c4  = idx & (LANES - 1);
        __stcs(&sou[(size_t)row * (ENC_IN / 4) + c4], zero);
    }

    // ---- Reduction over L: 32 rows/thread, streaming loads ----
    const float4* __restrict__ px =
        reinterpret_cast<const float4*>(x_enc + (size_t)b * SEQ_LEN * ENC_IN + c0);

    float4 sy  = zero;
    float4 sty = zero;
    #pragma unroll 4
    for (int i = 0; i < ROWS_PER_THREAD; ++i) {
        int r = i * NSUB + rsub;
        float4 v = __ldcs(&px[(size_t)r * (ENC_IN / 4) + lane]);
        float tc = (float)(r - SEQ_LEN);          // t in [-512, -1]
        sy.x += v.x;  sy.y += v.y;  sy.z += v.z;  sy.w += v.w;
        sty.x = fmaf(tc, v.x, sty.x);
        sty.y = fmaf(tc, v.y, sty.y);
        sty.z = fmaf(tc, v.z, sty.z);
        sty.w = fmaf(tc, v.w, sty.w);
    }

    __shared__ float4 red_sy[NSUB][LANES];
    __shared__ float4 red_sty[NSUB][LANES];
    __shared__ float4 sI4[LANES];
    __shared__ float4 sS4[LANES];

    red_sy[rsub][lane]  = sy;
    red_sty[rsub][lane] = sty;
    __syncthreads();

    if (t < LANES) {
        float4 a = red_sy[0][t];
        float4 c = red_sty[0][t];
        #pragma unroll
        for (int k = 1; k < NSUB; ++k) {
            float4 u = red_sy[k][t];
            float4 w = red_sty[k][t];
            a.x += u.x; a.y += u.y; a.z += u.z; a.w += u.w;
            c.x += w.x; c.y += w.y; c.z += w.z; c.w += w.w;
        }
        // Normal-equation constants for t = -512..-1 (exact in fp32):
        const float S0  = 512.0f;
        const float S1  = -131328.0f;
        const float S2  = 44870400.0f;
        const float det = 5726601216.0f;

        float4 I, S;
        I.x = (S2 * a.x - S1 * c.x) / det;  S.x = (S0 * c.x - S1 * a.x) / det;
        I.y = (S2 * a.y - S1 * c.y) / det;  S.y = (S0 * c.y - S1 * a.y) / det;
        I.z = (S2 * a.z - S1 * c.z) / det;  S.z = (S0 * c.z - S1 * a.z) / det;
        I.w = (S2 * a.w - S1 * c.w) / det;  S.w = (S0 * c.w - S1 * a.w) / det;
        sI4[t] = I;
        sS4[t] = S;
    }
    __syncthreads();

    // ---- Write dec_out and t_out (identical values), streaming stores ----
    float4* __restrict__ dec = reinterpret_cast<float4*>(out + tile_f);
    float4* __restrict__ tou = reinterpret_cast<float4*>(out + SEC + tile_f);

    #pragma unroll 4
    for (int idx = t; idx < PRED_LEN * LANES; idx += NT) {
        int row = idx >> 4;
        int c4  = idx & (LANES - 1);
        float tn = (float)(SEQ_LEN - PRED_LEN + row);   // 320..511
        float4 I = sI4[c4];
        float4 S = sS4[c4];
        float4 v;
        v.x = fmaf(S.x, tn, I.x);
        v.y = fmaf(S.y, tn, I.y);
        v.z = fmaf(S.z, tn, I.z);
        v.w = fmaf(S.w, tn, I.w);
        size_t off = (size_t)row * (ENC_IN / 4) + c4;
        __stcs(&dec[off], v);
        __stcs(&tou[off], v);
    }

    // ---- s_out zeros, second half (rows 96..191) ----
    #pragma unroll
    for (int idx = t; idx < (PRED_LEN / 2) * LANES; idx += NT) {
        int row = (idx >> 4) + PRED_LEN / 2;
        int c4  = idx & (LANES - 1);
        __stcs(&sou[(size_t)row * (ENC_IN / 4) + c4], zero);
    }
}

extern "C" void kernel_launch(void* const* d_in, const int* in_sizes, int n_in,
                              void* d_out, int out_size) {
    const float* x_enc = (const float*)d_in[0];
    float* out = (float*)d_out;
    fused_trend_kernel<<<dim3(BATCH, CSPLIT), NT>>>(x_enc, out);
}